// round 9
// baseline (speedup 1.0000x reference)
#include <cuda_runtime.h>

// VQC statevector simulator: 12 qubits, batch 1024, one CTA per batch element.
// Qubit q <-> index bit (11-q). State lives in skewed shared memory.
//
// Circuit (after folding):
//   init: amp(i) = prod_q v_q[bit_q(i)]   (enc H+Z^x and ansatz layer0 Y,Z folded)
//   CNOT chain #1 == Gray permutation, fused into init write
//   layer 1 (Y^t then Z^t per qubit): 3 passes of 4 fused qubits
//   CNOT chain #2: fused into layer-2 first pass as gather
//   layer 2 (Y^t only; Z^t dropped, doesn't affect probs): 3 passes
//   readout fused into final pass.

#define SK(i) ((i) + ((i) >> 4))   // skew: pad one float2 per 16 -> conflict-free strides

__device__ __forceinline__ float2 cmul(float2 a, float2 b) {
    return make_float2(a.x * b.x - a.y * b.y, a.x * b.y + a.y * b.x);
}

template<int B>
__device__ __forceinline__ int pass_base(int t) {
    if (B == 0) return t << 4;                       // group bits 0..3, t -> bits 4..11
    if (B == 4) return (t & 15) | ((t >> 4) << 8);   // group bits 4..7
    return t;                                        // B == 8: group bits 8..11
}

// Fused Y^t then Z^t gate on 4 qubits (global bits B..B+3), in-register.
// a[m] indexed by the 4 group bits; m-bit lb == index bit (B+lb) == qubit (11-B-lb).
template<int B>
__device__ __forceinline__ void gates_l2(float2* a,
                                         const float* __restrict__ c2,
                                         const float* __restrict__ s2,
                                         const float* __restrict__ zr,
                                         const float* __restrict__ zi) {
#pragma unroll
    for (int lb = 0; lb < 4; ++lb) {
        const int q = 11 - (B + lb);
        const float c = c2[q], sn = s2[q], pr = zr[q], pi = zi[q];
#pragma unroll
        for (int m = 0; m < 16; ++m) {
            if (m & (1 << lb)) continue;
            const int mp = m | (1 << lb);
            float2 a0 = a[m], a1 = a[mp];
            float n0x = c * a0.x - sn * a1.x;
            float n0y = c * a0.y - sn * a1.y;
            float tx  = sn * a0.x + c * a1.x;
            float ty  = sn * a0.y + c * a1.y;
            a[m]  = make_float2(n0x, n0y);
            a[mp] = make_float2(pr * tx - pi * ty, pr * ty + pi * tx);
        }
    }
}

// Final layer: Y^t only (real rotation).
template<int B>
__device__ __forceinline__ void gates_l3(float2* a,
                                         const float* __restrict__ c3,
                                         const float* __restrict__ s3) {
#pragma unroll
    for (int lb = 0; lb < 4; ++lb) {
        const int q = 11 - (B + lb);
        const float c = c3[q], sn = s3[q];
#pragma unroll
        for (int m = 0; m < 16; ++m) {
            if (m & (1 << lb)) continue;
            const int mp = m | (1 << lb);
            float2 a0 = a[m], a1 = a[mp];
            a[m]  = make_float2(c * a0.x - sn * a1.x, c * a0.y - sn * a1.y);
            a[mp] = make_float2(sn * a0.x + c * a1.x, sn * a0.y + c * a1.y);
        }
    }
}

__global__ void __launch_bounds__(256, 4)
vqc_kernel(const float* __restrict__ inputs,
           const float* __restrict__ thetas,
           float* __restrict__ out)
{
    __shared__ float2 st[4096 + 256];
    __shared__ float2 vq[12][2];
    __shared__ float c2s[12], s2s[12], p2rs[12], p2is[12], c3s[12], s3s[12];
    __shared__ float2 tab[3][16];   // [0]=bits0..3(q11..8) [1]=bits4..7(q7..4) [2]=bits8..11(q3..0)
    __shared__ float red[8][12];

    const int t = threadIdx.x;
    const int b = blockIdx.x;

    // ---- Phase 0a: per-qubit folded init vector + layer params ----
    if (t < 12) {
        const int q = t;
        const float x  = inputs[b * 12 + q];
        const float t0 = thetas[2 * q];
        const float t1 = thetas[2 * q + 1];
        float s0, c0;  sincospif(0.5f * t0, &s0, &c0);
        float exi, exr; sincospif(x, &exi, &exr);           // e^{i pi x}
        float p1i, p1r; sincospif(t1, &p1i, &p1r);          // e^{i pi t1}
        const float inv = 0.70710678118654752f;
        // v = Z(t1) * Y(t0) * diag(1, e^{i pi x}) * H * e0
        float u0r = (c0 - s0 * exr) * inv, u0i = (-s0 * exi) * inv;
        float w1r = (s0 + c0 * exr) * inv, w1i = (c0 * exi) * inv;
        vq[q][0] = make_float2(u0r, u0i);
        vq[q][1] = make_float2(w1r * p1r - w1i * p1i, w1r * p1i + w1i * p1r);
        // layer 1 (second ansatz layer) params
        float sa, ca; sincospif(0.5f * thetas[24 + 2 * q], &sa, &ca);
        c2s[q] = ca; s2s[q] = sa;
        float zi2, zr2; sincospif(thetas[24 + 2 * q + 1], &zi2, &zr2);
        p2rs[q] = zr2; p2is[q] = zi2;
        // layer 2 (last) params: only Y angle matters for Z readout
        float sb, cb; sincospif(0.5f * thetas[48 + 2 * q], &sb, &cb);
        c3s[q] = cb; s3s[q] = sb;
    }
    __syncthreads();

    // ---- Phase 0b: 16-entry sub-product tables (3x 4-qubit groups) ----
    if (t < 48) {
        const int which = t >> 4, m = t & 15;
        const int qtop = (which == 0) ? 11 : (which == 1 ? 7 : 3);
        float2 acc = make_float2(1.f, 0.f);
#pragma unroll
        for (int lb = 0; lb < 4; ++lb)
            acc = cmul(acc, vq[qtop - lb][(m >> lb) & 1]);
        tab[which][m] = acc;
    }
    __syncthreads();

    // ---- P1: init product state, fused with CNOT chain #1 (Gray perm) ----
    {
        const int base = t << 4;
#pragma unroll
        for (int jj = 0; jj < 16; ++jj) {
            const int j = base + jj;
            const int g = j ^ (j >> 1);        // pre-CNOT source index
            float2 amp = cmul(cmul(tab[2][(g >> 8) & 15], tab[1][(g >> 4) & 15]),
                              tab[0][g & 15]);
            st[SK(j)] = amp;
        }
    }
    __syncthreads();

    // ---- Layer 1 (Y,Z) : three 4-qubit passes ----
    {
        float2 a[16];
        const int base = pass_base<0>(t);
#pragma unroll
        for (int m = 0; m < 16; ++m) a[m] = st[SK(base + m)];
        gates_l2<0>(a, c2s, s2s, p2rs, p2is);
#pragma unroll
        for (int m = 0; m < 16; ++m) st[SK(base + m)] = a[m];
    }
    __syncthreads();
    {
        float2 a[16];
        const int base = pass_base<4>(t);
#pragma unroll
        for (int m = 0; m < 16; ++m) a[m] = st[SK(base + (m << 4))];
        gates_l2<4>(a, c2s, s2s, p2rs, p2is);
#pragma unroll
        for (int m = 0; m < 16; ++m) st[SK(base + (m << 4))] = a[m];
    }
    __syncthreads();
    {
        float2 a[16];
        const int base = pass_base<8>(t);
#pragma unroll
        for (int m = 0; m < 16; ++m) a[m] = st[SK(base + (m << 8))];
        gates_l2<8>(a, c2s, s2s, p2rs, p2is);
#pragma unroll
        for (int m = 0; m < 16; ++m) st[SK(base + (m << 8))] = a[m];
    }
    __syncthreads();

    // ---- Layer 2 pass 1 (bits 0..3) with fused CNOT chain #2 gather ----
    {
        float2 a[16];
        const int base = pass_base<0>(t);
#pragma unroll
        for (int m = 0; m < 16; ++m) {
            const int i = base + m;
            const int g = i ^ (i >> 1);
            a[m] = st[SK(g)];
        }
        gates_l3<0>(a, c3s, s3s);
        __syncthreads();   // all gathers done before any scatter
#pragma unroll
        for (int m = 0; m < 16; ++m) st[SK(base + m)] = a[m];
    }
    __syncthreads();

    // ---- Layer 2 pass 2 (bits 4..7) ----
    {
        float2 a[16];
        const int base = pass_base<4>(t);
#pragma unroll
        for (int m = 0; m < 16; ++m) a[m] = st[SK(base + (m << 4))];
        gates_l3<4>(a, c3s, s3s);
#pragma unroll
        for (int m = 0; m < 16; ++m) st[SK(base + (m << 4))] = a[m];
    }
    __syncthreads();

    // ---- Layer 2 pass 3 (bits 8..11) + fused readout, no write-back ----
    float part[12];
    {
        float2 a[16];
        const int base = pass_base<8>(t);   // = t, covers index bits 0..7
#pragma unroll
        for (int m = 0; m < 16; ++m) a[m] = st[SK(base + (m << 8))];
        gates_l3<8>(a, c3s, s3s);

        float tot = 0.f;
        float sgn[4] = {0.f, 0.f, 0.f, 0.f};   // indexed by k = bit (8+k)
#pragma unroll
        for (int m = 0; m < 16; ++m) {
            const float p = a[m].x * a[m].x + a[m].y * a[m].y;
            tot += p;
#pragma unroll
            for (int k = 0; k < 4; ++k)
                sgn[k] += ((m >> k) & 1) ? -p : p;
        }
        // qubit q in 0..3 -> bit 11-q = 8 + (3-q) -> sgn[3-q]
#pragma unroll
        for (int q = 0; q < 4; ++q) part[q] = sgn[3 - q];
        // qubit q in 4..11 -> bit 11-q in 0..7, taken from t (constant over m)
#pragma unroll
        for (int q = 4; q < 12; ++q)
            part[q] = ((t >> (11 - q)) & 1) ? -tot : tot;
    }

    // ---- Block reduction of 12 expectation partials ----
#pragma unroll
    for (int q = 0; q < 12; ++q) {
        float v = part[q];
#pragma unroll
        for (int off = 16; off > 0; off >>= 1)
            v += __shfl_xor_sync(0xffffffffu, v, off);
        if ((t & 31) == 0) red[t >> 5][q] = v;
    }
    __syncthreads();
    if (t < 12) {
        float acc = 0.f;
#pragma unroll
        for (int w = 0; w < 8; ++w) acc += red[w][t];
        out[b * 12 + t] = acc;
    }
}

extern "C" void kernel_launch(void* const* d_in, const int* in_sizes, int n_in,
                              void* d_out, int out_size)
{
    const float* inputs = (const float*)d_in[0];
    const float* thetas = (const float*)d_in[1];
    if (n_in >= 2 && in_sizes[0] == 72 && in_sizes[1] != 72) {
        // defensive: metadata order swapped
        const float* tmp = inputs; inputs = thetas; thetas = tmp;
        const int batch = in_sizes[1] / 12;
        vqc_kernel<<<batch, 256>>>(inputs, thetas, (float*)d_out);
        return;
    }
    const int batch = in_sizes[0] / 12;
    vqc_kernel<<<batch, 256>>>(inputs, thetas, (float*)d_out);
}

// round 10
// speedup vs baseline: 1.1523x; 1.1523x over previous
#include <cuda_runtime.h>

// VQC statevector simulator: 12 qubits, batch 1024, one CTA per batch element.
// Qubit q <-> index bit (11-q). State in skewed shared memory.
//
// R10: packed f32x2 butterflies (FFMA2), batched Z-diagonal per pass,
//      init fused into layer-1 pass 0 (one fewer shared round trip + sync).

typedef unsigned long long ull;

#define SK(i) ((i) + ((i) >> 4))   // skew: conflict-free for stride 16/256 patterns

__device__ __forceinline__ float2 cmul(float2 a, float2 b) {
    return make_float2(a.x * b.x - a.y * b.y, a.x * b.y + a.y * b.x);
}
__device__ __forceinline__ ull pk2(float x, float y) {
    ull r; asm("mov.b64 %0, {%1,%2};" : "=l"(r) : "f"(x), "f"(y)); return r;
}
__device__ __forceinline__ float2 upk(ull v) {
    float2 r; asm("mov.b64 {%0,%1}, %2;" : "=f"(r.x), "=f"(r.y) : "l"(v)); return r;
}
__device__ __forceinline__ ull mul2(ull a, ull b) {
    ull d; asm("mul.rn.f32x2 %0, %1, %2;" : "=l"(d) : "l"(a), "l"(b)); return d;
}
__device__ __forceinline__ ull fma2(ull a, ull b, ull c) {
    ull d; asm("fma.rn.f32x2 %0, %1, %2, %3;" : "=l"(d) : "l"(a), "l"(b), "l"(c)); return d;
}

template<int B>
__device__ __forceinline__ int pass_base(int t) {
    if (B == 0) return t << 4;                       // group bits 0..3
    if (B == 4) return (t & 15) | ((t >> 4) << 8);   // group bits 4..7
    return t;                                        // B == 8: group bits 8..11
}

// Packed Y^t butterflies on 4 qubits (global bits B..B+3), amplitudes in ull (re,im).
template<int B>
__device__ __forceinline__ void y4(ull* a,
                                   const ull* __restrict__ cp,
                                   const ull* __restrict__ sp,
                                   const ull* __restrict__ nsp) {
#pragma unroll
    for (int lb = 0; lb < 4; ++lb) {
        const int q = 11 - (B + lb);
        const ull cc = cp[q], ss = sp[q], ns = nsp[q];
#pragma unroll
        for (int m = 0; m < 16; ++m) {
            if (m & (1 << lb)) continue;
            const int mp = m | (1 << lb);
            ull u0 = a[m], u1 = a[mp];
            a[m]  = fma2(ns, u1, mul2(cc, u0));   // c*a0 - s*a1
            a[mp] = fma2(ss, u0, mul2(cc, u1));   // s*a0 + c*a1
        }
    }
}

__global__ void __launch_bounds__(256, 4)
vqc_kernel(const float* __restrict__ inputs,
           const float* __restrict__ thetas,
           float* __restrict__ out)
{
    __shared__ float2 st[4096 + 256];
    __shared__ float2 vq[12][2];
    __shared__ ull c2p[12], s2p[12], ns2p[12];    // layer-1 Y, packed (v,v)
    __shared__ ull c3p[12], s3p[12], ns3p[12];    // layer-2 Y, packed
    __shared__ float p2r[12], p2i[12];            // layer-1 Z phases (scalar, for tables)
    __shared__ float2 tab[3][16];                 // init sub-products
    __shared__ float2 ph[3][16];                  // layer-1 group Z-phase per pass
    __shared__ float red[8][12];

    const int t = threadIdx.x;
    const int b = blockIdx.x;

    // ---- Phase 0a: per-qubit folded init vector + layer params ----
    if (t < 12) {
        const int q = t;
        const float x  = inputs[b * 12 + q];
        const float t0 = thetas[2 * q];
        const float t1 = thetas[2 * q + 1];
        float s0, c0;  sincospif(0.5f * t0, &s0, &c0);
        float exi, exr; sincospif(x, &exi, &exr);           // e^{i pi x}
        float p1i, p1r; sincospif(t1, &p1i, &p1r);          // e^{i pi t1}
        const float inv = 0.70710678118654752f;
        // v = Z(t1) * Y(t0) * diag(1, e^{i pi x}) * H * e0
        float u0r = (c0 - s0 * exr) * inv, u0i = (-s0 * exi) * inv;
        float w1r = (s0 + c0 * exr) * inv, w1i = (c0 * exi) * inv;
        vq[q][0] = make_float2(u0r, u0i);
        vq[q][1] = make_float2(w1r * p1r - w1i * p1i, w1r * p1i + w1i * p1r);
        // layer 1 params
        float sa, ca; sincospif(0.5f * thetas[24 + 2 * q], &sa, &ca);
        c2p[q] = pk2(ca, ca); s2p[q] = pk2(sa, sa); ns2p[q] = pk2(-sa, -sa);
        float zi2, zr2; sincospif(thetas[24 + 2 * q + 1], &zi2, &zr2);
        p2r[q] = zr2; p2i[q] = zi2;
        // layer 2 params (Z^t dropped: diagonal doesn't change |amp|^2)
        float sb, cb; sincospif(0.5f * thetas[48 + 2 * q], &sb, &cb);
        c3p[q] = pk2(cb, cb); s3p[q] = pk2(sb, sb); ns3p[q] = pk2(-sb, -sb);
    }
    __syncthreads();

    // ---- Phase 0b: init sub-product tables + layer-1 Z group-phase tables ----
    if (t < 48) {
        const int which = t >> 4, m = t & 15;
        // init product table: tab[0]=bits0..3(q11..8), [1]=bits4..7, [2]=bits8..11
        const int qtop = (which == 0) ? 11 : (which == 1 ? 7 : 3);
        float2 acc = make_float2(1.f, 0.f);
#pragma unroll
        for (int lb = 0; lb < 4; ++lb)
            acc = cmul(acc, vq[qtop - lb][(m >> lb) & 1]);
        tab[which][m] = acc;
        // Z-phase table for pass `which` (covers global bits 4*which..4*which+3)
        float2 pz = make_float2(1.f, 0.f);
#pragma unroll
        for (int lb = 0; lb < 4; ++lb) {
            if ((m >> lb) & 1) {
                const int q = 11 - (4 * which + lb);
                pz = cmul(pz, make_float2(p2r[q], p2i[q]));
            }
        }
        ph[which][m] = pz;
    }
    __syncthreads();

    // ---- Fused: init product state + CNOT chain #1 (Gray) + Layer-1 pass 0 ----
    {
        ull a[16];
        const int base = t << 4;
        const int gh = t ^ (t >> 1);                        // g bits 4..11 (const over m)
        const float2 ab = cmul(tab[2][(gh >> 4) & 15], tab[1][gh & 15]);
        const int x3 = (t & 1) << 3;                        // g bit 3 gets j bit 4
#pragma unroll
        for (int m = 0; m < 16; ++m) {
            const int gl = (m ^ (m >> 1)) ^ x3;
            const float2 amp = cmul(ab, tab[0][gl]);
            a[m] = pk2(amp.x, amp.y);
        }
        y4<0>(a, c2p, s2p, ns2p);
#pragma unroll
        for (int m = 0; m < 16; ++m)
            st[SK(base + m)] = cmul(upk(a[m]), ph[0][m]);   // batched Z diagonal
    }
    __syncthreads();

    // ---- Layer-1 pass 1 (bits 4..7) ----
    {
        ull a[16];
        const int base = pass_base<4>(t);
#pragma unroll
        for (int m = 0; m < 16; ++m)
            a[m] = *reinterpret_cast<const ull*>(&st[SK(base + (m << 4))]);
        y4<4>(a, c2p, s2p, ns2p);
#pragma unroll
        for (int m = 0; m < 16; ++m)
            st[SK(base + (m << 4))] = cmul(upk(a[m]), ph[1][m]);
    }
    __syncthreads();

    // ---- Layer-1 pass 2 (bits 8..11) ----
    {
        ull a[16];
        const int base = pass_base<8>(t);
#pragma unroll
        for (int m = 0; m < 16; ++m)
            a[m] = *reinterpret_cast<const ull*>(&st[SK(base + (m << 8))]);
        y4<8>(a, c2p, s2p, ns2p);
#pragma unroll
        for (int m = 0; m < 16; ++m)
            st[SK(base + (m << 8))] = cmul(upk(a[m]), ph[2][m]);
    }
    __syncthreads();

    // ---- Layer-2 pass 0 (bits 0..3) with fused CNOT chain #2 (Gray gather) ----
    {
        ull a[16];
        const int base = t << 4;
        const int gh = t ^ (t >> 1);
        const int x3 = (t & 1) << 3;
#pragma unroll
        for (int m = 0; m < 16; ++m) {
            const int g = (gh << 4) | ((m ^ (m >> 1)) ^ x3);
            a[m] = *reinterpret_cast<const ull*>(&st[SK(g)]);
        }
        y4<0>(a, c3p, s3p, ns3p);
        __syncthreads();   // all gathers done before any scatter
#pragma unroll
        for (int m = 0; m < 16; ++m)
            *reinterpret_cast<ull*>(&st[SK(base + m)]) = a[m];
    }
    __syncthreads();

    // ---- Layer-2 pass 1 (bits 4..7) ----
    {
        ull a[16];
        const int base = pass_base<4>(t);
#pragma unroll
        for (int m = 0; m < 16; ++m)
            a[m] = *reinterpret_cast<const ull*>(&st[SK(base + (m << 4))]);
        y4<4>(a, c3p, s3p, ns3p);
#pragma unroll
        for (int m = 0; m < 16; ++m)
            *reinterpret_cast<ull*>(&st[SK(base + (m << 4))]) = a[m];
    }
    __syncthreads();

    // ---- Layer-2 pass 2 (bits 8..11) + fused readout (no write-back) ----
    float part[12];
    {
        ull a[16];
        const int base = pass_base<8>(t);   // = t, covers index bits 0..7
#pragma unroll
        for (int m = 0; m < 16; ++m)
            a[m] = *reinterpret_cast<const ull*>(&st[SK(base + (m << 8))]);
        y4<8>(a, c3p, s3p, ns3p);

        float tot = 0.f;
        float sgn[4] = {0.f, 0.f, 0.f, 0.f};   // k = bit (8+k)
#pragma unroll
        for (int m = 0; m < 16; ++m) {
            const float2 v = upk(a[m]);
            const float p = v.x * v.x + v.y * v.y;
            tot += p;
#pragma unroll
            for (int k = 0; k < 4; ++k)
                sgn[k] += ((m >> k) & 1) ? -p : p;
        }
#pragma unroll
        for (int q = 0; q < 4; ++q) part[q] = sgn[3 - q];
#pragma unroll
        for (int q = 4; q < 12; ++q)
            part[q] = ((t >> (11 - q)) & 1) ? -tot : tot;
    }

    // ---- Block reduction of 12 expectation partials ----
#pragma unroll
    for (int q = 0; q < 12; ++q) {
        float v = part[q];
#pragma unroll
        for (int off = 16; off > 0; off >>= 1)
            v += __shfl_xor_sync(0xffffffffu, v, off);
        if ((t & 31) == 0) red[t >> 5][q] = v;
    }
    __syncthreads();
    if (t < 12) {
        float acc = 0.f;
#pragma unroll
        for (int w = 0; w < 8; ++w) acc += red[w][t];
        out[b * 12 + t] = acc;
    }
}

extern "C" void kernel_launch(void* const* d_in, const int* in_sizes, int n_in,
                              void* d_out, int out_size)
{
    const float* inputs = (const float*)d_in[0];
    const float* thetas = (const float*)d_in[1];
    if (n_in >= 2 && in_sizes[0] == 72 && in_sizes[1] != 72) {
        const float* tmp = inputs; inputs = thetas; thetas = tmp;
        const int batch = in_sizes[1] / 12;
        vqc_kernel<<<batch, 256>>>(inputs, thetas, (float*)d_out);
        return;
    }
    const int batch = in_sizes[0] / 12;
    vqc_kernel<<<batch, 256>>>(inputs, thetas, (float*)d_out);
}